// round 14
// baseline (speedup 1.0000x reference)
#include <cuda_runtime.h>

#define ALPHA_F 0.1f
#define OMA_F   0.9f
// B=64, T=512, D_IN=256, H=1024, D_OUT=256

// -------- scratch (static device arrays; no runtime allocation) --------
__device__ float g_U[512 * 64 * 1024];   // 128 MB: input drive U[t][b][h]
__device__ float g_P[16 * 64 * 1024];    // 4 MB:  K-split partials P[kc][b][h]
__device__ float g_V0[64 * 1024];        // layer-0 membrane potential
__device__ float g_V1[64 * 1024];        // layer-1 membrane potential

// -------- software grid barrier state (gen-relative; survives replays) ------
__device__ volatile unsigned g_gen;
__device__ unsigned g_cnt;

// -------- packed fp32x2 helpers (sm_100+ PTX) --------
__device__ __forceinline__ unsigned long long pack2(float x, float y) {
    unsigned long long r;
    asm("mov.b64 %0, {%1, %2};" : "=l"(r) : "f"(x), "f"(y));
    return r;
}
__device__ __forceinline__ void fma2(unsigned long long& d,
                                     unsigned long long a, unsigned long long b) {
    asm("fma.rn.f32x2 %0, %1, %2, %0;" : "+l"(d) : "l"(a), "l"(b));
}
__device__ __forceinline__ float2 unpack2(unsigned long long v) {
    float2 f;
    asm("mov.b64 {%0, %1}, %2;" : "=f"(f.x), "=f"(f.y) : "l"(v));
    return f;
}

// grid-wide barrier for NCTAS co-resident CTAs
template <int NCTAS>
__device__ __forceinline__ void grid_bar() {
    __syncthreads();
    if (threadIdx.x == 0) {
        __threadfence();                       // publish this CTA's stores
        unsigned my = g_gen;                   // read BEFORE arriving
        if (atomicAdd(&g_cnt, 1) == NCTAS - 1) {
            g_cnt = 0;
            __threadfence();
            atomicAdd((unsigned*)&g_gen, 1);
        } else {
            while (g_gen == my) { }
        }
        __threadfence();                       // acquire others' stores
    }
    __syncthreads();
}

// ============================================================================
// Big parallel GEMM with bias: C[r][n] = sum_k A_row(r)[k] * W[n][k] + bias[n]
// CTA tile 128x128, kc=8, 256 threads, 8x8 microkernel with packed f32x2 FMA.
// SWAP: logical row r = t*64+b maps to A row (b*512 + t).
// ============================================================================
template <bool SWAP>
__global__ __launch_bounds__(256) void gemm_bias(
    const float* __restrict__ A, const float* __restrict__ W,
    const float* __restrict__ bias, float* __restrict__ C,
    int N, int K)
{
    __shared__ float As[8][128];
    __shared__ float Ws[8][128];

    const int tid = threadIdx.x;
    const int tx = tid & 15;        // n direction (8 outputs)
    const int ty = tid >> 4;        // m direction (8 outputs)
    const int m0 = blockIdx.y * 128;
    const int n0 = blockIdx.x * 128;

    const int lm = tid >> 1;              // 0..127: row within tile
    const int lk = (tid & 1) * 4;         // 0 or 4
    const int r = m0 + lm;
    long aoff;
    if (SWAP) aoff = ((long)(r & 63) * 512 + (r >> 6)) * (long)K;
    else      aoff = (long)r * K;
    const long woff = (long)(n0 + lm) * K;

    unsigned long long acc[8][4];
#pragma unroll
    for (int i = 0; i < 8; i++)
#pragma unroll
        for (int j = 0; j < 4; j++) acc[i][j] = 0ull;

    for (int k0 = 0; k0 < K; k0 += 8) {
        const float4 a = *reinterpret_cast<const float4*>(A + aoff + k0 + lk);
        const float4 w = *reinterpret_cast<const float4*>(W + woff + k0 + lk);
        __syncthreads();
        As[lk + 0][lm] = a.x; As[lk + 1][lm] = a.y;
        As[lk + 2][lm] = a.z; As[lk + 3][lm] = a.w;
        Ws[lk + 0][lm] = w.x; Ws[lk + 1][lm] = w.y;
        Ws[lk + 2][lm] = w.z; Ws[lk + 3][lm] = w.w;
        __syncthreads();
#pragma unroll
        for (int kk = 0; kk < 8; kk++) {
            const float4 a0 = *reinterpret_cast<const float4*>(&As[kk][ty * 8]);
            const float4 a1 = *reinterpret_cast<const float4*>(&As[kk][ty * 8 + 4]);
            const ulonglong2 w0 = *reinterpret_cast<const ulonglong2*>(&Ws[kk][tx * 8]);
            const ulonglong2 w1 = *reinterpret_cast<const ulonglong2*>(&Ws[kk][tx * 8 + 4]);
            const float av[8] = {a0.x, a0.y, a0.z, a0.w, a1.x, a1.y, a1.z, a1.w};
            const unsigned long long wp[4] = {w0.x, w0.y, w1.x, w1.y};
#pragma unroll
            for (int i = 0; i < 8; i++) {
                const unsigned long long ad = pack2(av[i], av[i]);
                fma2(acc[i][0], ad, wp[0]);
                fma2(acc[i][1], ad, wp[1]);
                fma2(acc[i][2], ad, wp[2]);
                fma2(acc[i][3], ad, wp[3]);
            }
        }
    }

    float bj[8];
#pragma unroll
    for (int j = 0; j < 8; j++) bj[j] = bias[n0 + tx * 8 + j];

#pragma unroll
    for (int i = 0; i < 8; i++) {
        const long m = m0 + ty * 8 + i;
        float* crow = C + m * (long)N + n0 + tx * 8;
        float o[8];
#pragma unroll
        for (int j = 0; j < 4; j++) {
            const float2 f = unpack2(acc[i][j]);
            o[2 * j]     = f.x + bj[2 * j];
            o[2 * j + 1] = f.y + bj[2 * j + 1];
        }
        *reinterpret_cast<float4*>(crow)     = make_float4(o[0], o[1], o[2], o[3]);
        *reinterpret_cast<float4*>(crow + 4) = make_float4(o[4], o[5], o[6], o[7]);
    }
}

// ============================================================================
// Persistent scan kernel: runs all 512 timesteps of one leaky-CTRNN layer.
// 128 CTAs x 128 threads. CTA (ht = bid&7, kc = bid>>3) owns a fixed
// 128h x 64k slice of W_rec (preloaded in smem once).
// Per step: phase A: partial rec-GEMM -> g_P;  grid barrier;
//           phase B: reduce partials + leak integrate + relu -> V, states;
//           grid barrier.
// states layout: [B=64][T=512][H=1024].
// ============================================================================
__global__ __launch_bounds__(128) void scan_layer(
    const float* __restrict__ U, const float* __restrict__ Wrec,
    float* __restrict__ V, float* __restrict__ states)
{
    __shared__ float ws[64][128];   // ws[k][h]  32 KB  (resident whole kernel)
    __shared__ float fs[64][64];    // fs[k][b]  16 KB  (reloaded each step)

    const int tid = threadIdx.x;
    const int ht = blockIdx.x & 7;
    const int kc = blockIdx.x >> 3;
    const int hT = ht * 128;
    const int k0 = kc * 64;

    // preload W tile (128 h x 64 k), transposed into smem — once
#pragma unroll
    for (int j = 0; j < 16; j++) {
        const int q = tid + 128 * j;     // 0..2047 float4s
        const int h = q & 127;
        const int kq = q >> 7;           // 0..15
        const float4 v = *reinterpret_cast<const float4*>(
            Wrec + (long)(hT + h) * 1024 + k0 + kq * 4);
        ws[kq * 4 + 0][h] = v.x;
        ws[kq * 4 + 1][h] = v.y;
        ws[kq * 4 + 2][h] = v.z;
        ws[kq * 4 + 3][h] = v.w;
    }

    const int tx = tid & 15;   // h: 16 x 8 = 128
    const int ty = tid >> 4;   // b: 8  x 8 = 64

    // phase-B assignment: 4 consecutive elements of the 64x1024 state plane
    const long eb = (long)blockIdx.x * 512 + tid * 4;
    const int ub_b = (int)(eb >> 10);
    const int ub_h = (int)(eb & 1023);

    for (int t = 0; t < 512; t++) {
        if (t > 0) {
            // ---- phase A: load fr(t-1) tile, GEMM, write partial ----
#pragma unroll
            for (int j = 0; j < 8; j++) {
                const int q = tid + 128 * j;   // 0..1023 float4s
                const int b = q & 63;
                const int kq = q >> 6;         // 0..15
                const float4 v = *reinterpret_cast<const float4*>(
                    states + ((long)b * 512 + (t - 1)) * 1024 + k0 + kq * 4);
                fs[kq * 4 + 0][b] = v.x;
                fs[kq * 4 + 1][b] = v.y;
                fs[kq * 4 + 2][b] = v.z;
                fs[kq * 4 + 3][b] = v.w;
            }
            __syncthreads();

            unsigned long long acc[8][4];
#pragma unroll
            for (int i = 0; i < 8; i++)
#pragma unroll
                for (int j = 0; j < 4; j++) acc[i][j] = 0ull;

#pragma unroll 8
            for (int k = 0; k < 64; k++) {
                const float4 a0 = *reinterpret_cast<const float4*>(&fs[k][ty * 8]);
                const float4 a1 = *reinterpret_cast<const float4*>(&fs[k][ty * 8 + 4]);
                const ulonglong2 w0 = *reinterpret_cast<const ulonglong2*>(&ws[k][tx * 8]);
                const ulonglong2 w1 = *reinterpret_cast<const ulonglong2*>(&ws[k][tx * 8 + 4]);
                const float av[8] = {a0.x, a0.y, a0.z, a0.w, a1.x, a1.y, a1.z, a1.w};
                const unsigned long long wp[4] = {w0.x, w0.y, w1.x, w1.y};
#pragma unroll
                for (int i = 0; i < 8; i++) {
                    const unsigned long long ad = pack2(av[i], av[i]);
                    fma2(acc[i][0], ad, wp[0]);
                    fma2(acc[i][1], ad, wp[1]);
                    fma2(acc[i][2], ad, wp[2]);
                    fma2(acc[i][3], ad, wp[3]);
                }
            }

#pragma unroll
            for (int i = 0; i < 8; i++) {
                const int b = ty * 8 + i;
                ulonglong2* p = reinterpret_cast<ulonglong2*>(
                    g_P + ((long)kc * 64 + b) * 1024 + hT + tx * 8);
                p[0] = make_ulonglong2(acc[i][0], acc[i][1]);
                p[1] = make_ulonglong2(acc[i][2], acc[i][3]);
            }
        }

        grid_bar<128>();   // partials visible (also syncs fs for next overwrite)

        // ---- phase B: reduce partials, leak integrate, relu, store ----
        {
            float4 rec = make_float4(0.f, 0.f, 0.f, 0.f);
            if (t > 0) {
#pragma unroll
                for (int c = 0; c < 16; c++) {
                    const float4 pv = *reinterpret_cast<const float4*>(
                        g_P + (long)c * 65536 + eb);
                    rec.x += pv.x; rec.y += pv.y; rec.z += pv.z; rec.w += pv.w;
                }
            }
            const float4 u = *reinterpret_cast<const float4*>(U + (long)t * 65536 + eb);
            float4 vn;
            if (t > 0) {
                const float4 vo = *reinterpret_cast<const float4*>(V + eb);
                vn.x = OMA_F * vo.x + ALPHA_F * (u.x + rec.x);
                vn.y = OMA_F * vo.y + ALPHA_F * (u.y + rec.y);
                vn.z = OMA_F * vo.z + ALPHA_F * (u.z + rec.z);
                vn.w = OMA_F * vo.w + ALPHA_F * (u.w + rec.w);
            } else {
                vn.x = ALPHA_F * u.x; vn.y = ALPHA_F * u.y;
                vn.z = ALPHA_F * u.z; vn.w = ALPHA_F * u.w;
            }
            *reinterpret_cast<float4*>(V + eb) = vn;
            const float4 fr = make_float4(fmaxf(vn.x, 0.f), fmaxf(vn.y, 0.f),
                                          fmaxf(vn.z, 0.f), fmaxf(vn.w, 0.f));
            *reinterpret_cast<float4*>(
                states + ((long)ub_b * 512 + t) * 1024 + ub_h) = fr;
        }

        grid_bar<128>();   // states(t) visible before next step's fr loads
    }
}

// ============================================================================
// 5 graph nodes total: gemm -> scan -> gemm -> scan -> gemm
// d_out layout: [output 64*512*256][states0 64*512*1024][states1 64*512*1024]
// ============================================================================
extern "C" void kernel_launch(void* const* d_in, const int* in_sizes, int n_in,
                              void* d_out, int out_size)
{
    (void)in_sizes; (void)n_in; (void)out_size;

    const float* x      = (const float*)d_in[0];
    const float* W_in0  = (const float*)d_in[1];
    const float* W_rec0 = (const float*)d_in[2];
    const float* b0     = (const float*)d_in[3];
    const float* W_in1  = (const float*)d_in[4];
    const float* W_rec1 = (const float*)d_in[5];
    const float* b1     = (const float*)d_in[6];
    const float* W_out  = (const float*)d_in[7];
    const float* b_out  = (const float*)d_in[8];

    float* out     = (float*)d_out;
    float* states0 = out + (long)64 * 512 * 256;
    float* states1 = states0 + (long)64 * 512 * 1024;

    float *uptr, *v0, *v1;
    cudaGetSymbolAddress((void**)&uptr, g_U);
    cudaGetSymbolAddress((void**)&v0, g_V0);
    cudaGetSymbolAddress((void**)&v1, g_V1);

    // U0[t][b][:] = x[b][t][:] @ W_in0^T + b0
    gemm_bias<true><<<dim3(8, 256), 256>>>(x, W_in0, b0, uptr, 1024, 256);

    // layer 0 scan (persistent, all 512 steps)
    scan_layer<<<128, 128>>>(uptr, W_rec0, v0, states0);

    // U1[t][b][:] = states0[b][t][:] @ W_in1^T + b1
    gemm_bias<true><<<dim3(8, 256), 256>>>(states0, W_in1, b1, uptr, 1024, 1024);

    // layer 1 scan
    scan_layer<<<128, 128>>>(uptr, W_rec1, v1, states1);

    // output projection
    gemm_bias<false><<<dim3(2, 256), 256>>>(states1, W_out, b_out, out, 256, 1024);
}

// round 15
// speedup vs baseline: 1.0661x; 1.0661x over previous
#include <cuda_runtime.h>

#define ALPHA_F 0.1f
#define OMA_F   0.9f
// B=64, T=512, D_IN=256, H=1024, D_OUT=256

// -------- scratch (static device arrays; no runtime allocation) --------
__device__ float g_U [512 * 64 * 1024];  // 128 MB: layer-0 input drive U0[t][b][h]
__device__ float g_P0[16 * 64 * 1024];   // 4 MB: rec0 partials
__device__ float g_Q [16 * 64 * 1024];   // 4 MB: fr0 @ W_in1^T partials
__device__ float g_P1[16 * 64 * 1024];   // 4 MB: rec1 partials

// -------- software grid barrier state (gen-relative; survives replays) ------
__device__ volatile unsigned g_gen;
__device__ unsigned g_cnt;

// -------- packed fp32x2 helpers (sm_100+) --------
__device__ __forceinline__ unsigned long long pack2(float x, float y) {
    unsigned long long r;
    asm("mov.b64 %0, {%1, %2};" : "=l"(r) : "f"(x), "f"(y));
    return r;
}
__device__ __forceinline__ void fma2(unsigned long long& d,
                                     unsigned long long a, unsigned long long b) {
    asm("fma.rn.f32x2 %0, %1, %2, %0;" : "+l"(d) : "l"(a), "l"(b));
}
__device__ __forceinline__ float2 unpack2(unsigned long long v) {
    float2 f;
    asm("mov.b64 {%0, %1}, %2;" : "=f"(f.x), "=f"(f.y) : "l"(v));
    return f;
}

// grid-wide barrier for NCTAS co-resident CTAs (relative generation)
template <int NCTAS>
__device__ __forceinline__ void grid_bar() {
    __syncthreads();
    if (threadIdx.x == 0) {
        __threadfence();                       // publish this CTA's stores
        unsigned my = g_gen;                   // read BEFORE arriving
        if (atomicAdd(&g_cnt, 1) == NCTAS - 1) {
            g_cnt = 0;
            __threadfence();
            atomicAdd((unsigned*)&g_gen, 1);
        } else {
            while (g_gen == my) { }
        }
        __threadfence();                       // acquire others' stores
    }
    __syncthreads();
}

// ============================================================================
// Big parallel GEMM with bias: C[r][n] = sum_k A_row(r)[k] * W[n][k] + bias[n]
// CTA tile 128x128, kc=8, 256 threads, 8x8 microkernel, packed f32x2 FMA.
// SWAP: logical row r = t*64+b maps to A row (b*512 + t).
// ============================================================================
template <bool SWAP>
__global__ __launch_bounds__(256) void gemm_bias(
    const float* __restrict__ A, const float* __restrict__ W,
    const float* __restrict__ bias, float* __restrict__ C,
    int N, int K)
{
    __shared__ float As[8][128];
    __shared__ float Ws[8][128];

    const int tid = threadIdx.x;
    const int tx = tid & 15;
    const int ty = tid >> 4;
    const int m0 = blockIdx.y * 128;
    const int n0 = blockIdx.x * 128;

    const int lm = tid >> 1;
    const int lk = (tid & 1) * 4;
    const int r = m0 + lm;
    long aoff;
    if (SWAP) aoff = ((long)(r & 63) * 512 + (r >> 6)) * (long)K;
    else      aoff = (long)r * K;
    const long woff = (long)(n0 + lm) * K;

    unsigned long long acc[8][4];
#pragma unroll
    for (int i = 0; i < 8; i++)
#pragma unroll
        for (int j = 0; j < 4; j++) acc[i][j] = 0ull;

    for (int k0 = 0; k0 < K; k0 += 8) {
        const float4 a = *reinterpret_cast<const float4*>(A + aoff + k0 + lk);
        const float4 w = *reinterpret_cast<const float4*>(W + woff + k0 + lk);
        __syncthreads();
        As[lk + 0][lm] = a.x; As[lk + 1][lm] = a.y;
        As[lk + 2][lm] = a.z; As[lk + 3][lm] = a.w;
        Ws[lk + 0][lm] = w.x; Ws[lk + 1][lm] = w.y;
        Ws[lk + 2][lm] = w.z; Ws[lk + 3][lm] = w.w;
        __syncthreads();
#pragma unroll
        for (int kk = 0; kk < 8; kk++) {
            const float4 a0 = *reinterpret_cast<const float4*>(&As[kk][ty * 8]);
            const float4 a1 = *reinterpret_cast<const float4*>(&As[kk][ty * 8 + 4]);
            const ulonglong2 w0 = *reinterpret_cast<const ulonglong2*>(&Ws[kk][tx * 8]);
            const ulonglong2 w1 = *reinterpret_cast<const ulonglong2*>(&Ws[kk][tx * 8 + 4]);
            const float av[8] = {a0.x, a0.y, a0.z, a0.w, a1.x, a1.y, a1.z, a1.w};
            const unsigned long long wp[4] = {w0.x, w0.y, w1.x, w1.y};
#pragma unroll
            for (int i = 0; i < 8; i++) {
                const unsigned long long ad = pack2(av[i], av[i]);
                fma2(acc[i][0], ad, wp[0]);
                fma2(acc[i][1], ad, wp[1]);
                fma2(acc[i][2], ad, wp[2]);
                fma2(acc[i][3], ad, wp[3]);
            }
        }
    }

    float bj[8];
#pragma unroll
    for (int j = 0; j < 8; j++) bj[j] = bias[n0 + tx * 8 + j];

#pragma unroll
    for (int i = 0; i < 8; i++) {
        const long m = m0 + ty * 8 + i;
        float* crow = C + m * (long)N + n0 + tx * 8;
        float o[8];
#pragma unroll
        for (int j = 0; j < 4; j++) {
            const float2 f = unpack2(acc[i][j]);
            o[2 * j]     = f.x + bj[2 * j];
            o[2 * j + 1] = f.y + bj[2 * j + 1];
        }
        *reinterpret_cast<float4*>(crow)     = make_float4(o[0], o[1], o[2], o[3]);
        *reinterpret_cast<float4*>(crow + 4) = make_float4(o[4], o[5], o[6], o[7]);
    }
}

// ----------------------------------------------------------------------------
// 128h x 64b x 64k partial GEMM microkernel (8x8 register tile, f32x2).
// fs: smem [64k][64b], ws: smem [64k][128h]. Writes P[kc][b][hT + ...].
// ----------------------------------------------------------------------------
__device__ __forceinline__ void mm_tile(
    const float* __restrict__ fs, const float* __restrict__ ws,
    float* __restrict__ P, int kc, int hT, int tx, int ty)
{
    unsigned long long acc[8][4];
#pragma unroll
    for (int i = 0; i < 8; i++)
#pragma unroll
        for (int j = 0; j < 4; j++) acc[i][j] = 0ull;

#pragma unroll 8
    for (int k = 0; k < 64; k++) {
        const float4 a0 = *reinterpret_cast<const float4*>(fs + k * 64 + ty * 8);
        const float4 a1 = *reinterpret_cast<const float4*>(fs + k * 64 + ty * 8 + 4);
        const ulonglong2 w0 = *reinterpret_cast<const ulonglong2*>(ws + k * 128 + tx * 8);
        const ulonglong2 w1 = *reinterpret_cast<const ulonglong2*>(ws + k * 128 + tx * 8 + 4);
        const float av[8] = {a0.x, a0.y, a0.z, a0.w, a1.x, a1.y, a1.z, a1.w};
        const unsigned long long wp[4] = {w0.x, w0.y, w1.x, w1.y};
#pragma unroll
        for (int i = 0; i < 8; i++) {
            const unsigned long long ad = pack2(av[i], av[i]);
            fma2(acc[i][0], ad, wp[0]);
            fma2(acc[i][1], ad, wp[1]);
            fma2(acc[i][2], ad, wp[2]);
            fma2(acc[i][3], ad, wp[3]);
        }
    }

#pragma unroll
    for (int i = 0; i < 8; i++) {
        const int b = ty * 8 + i;
        ulonglong2* p = reinterpret_cast<ulonglong2*>(
            P + ((long)kc * 64 + b) * 1024 + hT + tx * 8);
        p[0] = make_ulonglong2(acc[i][0], acc[i][1]);
        p[1] = make_ulonglong2(acc[i][2], acc[i][3]);
    }
}

// load a 64b x 64k fr tile (transposed) from states[b][t][k0..] into smem fs
__device__ __forceinline__ void load_fs(
    float* __restrict__ fs, const float* __restrict__ states,
    int t, int k0, int tid)
{
#pragma unroll
    for (int j = 0; j < 8; j++) {
        const int q = tid + 128 * j;     // float4 index 0..1023
        const int b = q & 63;
        const int kq = q >> 6;           // 0..15
        const float4 v = *reinterpret_cast<const float4*>(
            states + ((long)b * 512 + t) * 1024 + k0 + kq * 4);
        fs[(kq * 4 + 0) * 64 + b] = v.x;
        fs[(kq * 4 + 1) * 64 + b] = v.y;
        fs[(kq * 4 + 2) * 64 + b] = v.z;
        fs[(kq * 4 + 3) * 64 + b] = v.w;
    }
}

// ============================================================================
// Fused persistent scan: BOTH layers, layer 1 pipelined one step behind.
// 128 CTAs x 128 threads; CTA (ht=bid&7, kc=bid>>3) holds 128h x 64k tiles of
// W_rec0, W_in1, W_rec1 in smem (96 KB) + two fs tiles (32 KB) -> 128 KB dyn.
// Step t (t = 0..512):
//   phase A: fs0 = fr0(t-1); P0 = fs0@Wrec0 (t in 1..511); Q(t-1) = fs0@Win1
//            (t>=1); fs1 = fr1(t-2); P1 = fs1@Wrec1 (t>=2).    grid barrier.
//   phase B: layer-0 update(t) with U0(t)+sum P0 (t<=511);
//            layer-1 update(t-1) with sum Q + sum P1 + b1 (t>=1). grid barrier.
// Membrane potentials v0, v1 live in registers (fixed per-thread elements).
// ============================================================================
__global__ __launch_bounds__(128) void fused_scan(
    const float* __restrict__ U, const float* __restrict__ Wrec0,
    const float* __restrict__ Win1, const float* __restrict__ Wrec1,
    const float* __restrict__ b1,
    float* __restrict__ states0, float* __restrict__ states1)
{
    extern __shared__ float sm[];
    float* ws0 = sm;                  // [64][128] Wrec0 tile
    float* wsQ = sm + 64 * 128;       // [64][128] Win1 tile
    float* ws1 = sm + 2 * 64 * 128;   // [64][128] Wrec1 tile
    float* fs0 = sm + 3 * 64 * 128;   // [64][64]  fr0 tile
    float* fs1 = fs0 + 64 * 64;       // [64][64]  fr1 tile

    const int tid = threadIdx.x;
    const int ht = blockIdx.x & 7;
    const int kc = blockIdx.x >> 3;
    const int hT = ht * 128;
    const int k0 = kc * 64;

    // ---- preload the three W tiles (transposed into smem), once ----
    {
        const float* Wsrc[3] = {Wrec0, Win1, Wrec1};
        float* Wdst[3] = {ws0, wsQ, ws1};
#pragma unroll
        for (int m = 0; m < 3; m++) {
#pragma unroll
            for (int j = 0; j < 16; j++) {
                const int q = tid + 128 * j;   // 0..2047 float4s
                const int h = q & 127;
                const int kq = q >> 7;         // 0..15
                const float4 v = *reinterpret_cast<const float4*>(
                    Wsrc[m] + (long)(hT + h) * 1024 + k0 + kq * 4);
                Wdst[m][(kq * 4 + 0) * 128 + h] = v.x;
                Wdst[m][(kq * 4 + 1) * 128 + h] = v.y;
                Wdst[m][(kq * 4 + 2) * 128 + h] = v.z;
                Wdst[m][(kq * 4 + 3) * 128 + h] = v.w;
            }
        }
    }

    const int tx = tid & 15;   // h: 16 x 8 = 128
    const int ty = tid >> 4;   // b: 8  x 8 = 64

    // phase-B ownership: 4 consecutive elements of the 64x1024 plane
    const long eb = (long)blockIdx.x * 512 + tid * 4;
    const int ub_b = (int)(eb >> 10);
    const int ub_h = (int)(eb & 1023);

    const float4 b1v = *reinterpret_cast<const float4*>(b1 + ub_h);
    float4 v0 = make_float4(0.f, 0.f, 0.f, 0.f);
    float4 v1 = make_float4(0.f, 0.f, 0.f, 0.f);

    for (int t = 0; t <= 512; t++) {
        // ---------------- phase A ----------------
        if (t >= 1) load_fs(fs0, states0, t - 1, k0, tid);
        if (t >= 2) load_fs(fs1, states1, t - 2, k0, tid);
        __syncthreads();

        if (t >= 1 && t <= 511) mm_tile(fs0, ws0, g_P0, kc, hT, tx, ty);
        if (t >= 1)             mm_tile(fs0, wsQ, g_Q,  kc, hT, tx, ty);
        if (t >= 2)             mm_tile(fs1, ws1, g_P1, kc, hT, tx, ty);

        grid_bar<128>();

        // ---------------- phase B ----------------
        if (t <= 511) {
            float4 rec = make_float4(0.f, 0.f, 0.f, 0.f);
            if (t >= 1) {
#pragma unroll
                for (int c = 0; c < 16; c++) {
                    const float4 pv = *reinterpret_cast<const float4*>(
                        g_P0 + (long)c * 65536 + eb);
                    rec.x += pv.x; rec.y += pv.y; rec.z += pv.z; rec.w += pv.w;
                }
            }
            const float4 u = *reinterpret_cast<const float4*>(U + (long)t * 65536 + eb);
            v0.x = OMA_F * v0.x + ALPHA_F * (u.x + rec.x);
            v0.y = OMA_F * v0.y + ALPHA_F * (u.y + rec.y);
            v0.z = OMA_F * v0.z + ALPHA_F * (u.z + rec.z);
            v0.w = OMA_F * v0.w + ALPHA_F * (u.w + rec.w);
            *reinterpret_cast<float4*>(
                states0 + ((long)ub_b * 512 + t) * 1024 + ub_h) =
                make_float4(fmaxf(v0.x, 0.f), fmaxf(v0.y, 0.f),
                            fmaxf(v0.z, 0.f), fmaxf(v0.w, 0.f));
        }
        if (t >= 1) {
            float4 s = b1v;
#pragma unroll
            for (int c = 0; c < 16; c++) {
                const float4 qv = *reinterpret_cast<const float4*>(
                    g_Q + (long)c * 65536 + eb);
                s.x += qv.x; s.y += qv.y; s.z += qv.z; s.w += qv.w;
            }
            if (t >= 2) {
#pragma unroll
                for (int c = 0; c < 16; c++) {
                    const float4 pv = *reinterpret_cast<const float4*>(
                        g_P1 + (long)c * 65536 + eb);
                    s.x += pv.x; s.y += pv.y; s.z += pv.z; s.w += pv.w;
                }
            }
            v1.x = OMA_F * v1.x + ALPHA_F * s.x;
            v1.y = OMA_F * v1.y + ALPHA_F * s.y;
            v1.z = OMA_F * v1.z + ALPHA_F * s.z;
            v1.w = OMA_F * v1.w + ALPHA_F * s.w;
            *reinterpret_cast<float4*>(
                states1 + ((long)ub_b * 512 + (t - 1)) * 1024 + ub_h) =
                make_float4(fmaxf(v1.x, 0.f), fmaxf(v1.y, 0.f),
                            fmaxf(v1.z, 0.f), fmaxf(v1.w, 0.f));
        }

        grid_bar<128>();
    }
}

// ============================================================================
// 3 graph nodes: U0 gemm -> fused scan (both layers) -> output gemm
// d_out layout: [output 64*512*256][states0 64*512*1024][states1 64*512*1024]
// ============================================================================
extern "C" void kernel_launch(void* const* d_in, const int* in_sizes, int n_in,
                              void* d_out, int out_size)
{
    (void)in_sizes; (void)n_in; (void)out_size;

    const float* x      = (const float*)d_in[0];
    const float* W_in0  = (const float*)d_in[1];
    const float* W_rec0 = (const float*)d_in[2];
    const float* b0     = (const float*)d_in[3];
    const float* W_in1  = (const float*)d_in[4];
    const float* W_rec1 = (const float*)d_in[5];
    const float* b1     = (const float*)d_in[6];
    const float* W_out  = (const float*)d_in[7];
    const float* b_out  = (const float*)d_in[8];

    float* out     = (float*)d_out;
    float* states0 = out + (long)64 * 512 * 256;
    float* states1 = states0 + (long)64 * 512 * 1024;

    float* uptr;
    cudaGetSymbolAddress((void**)&uptr, g_U);

    const int smem_bytes = 32768 * sizeof(float);   // 128 KB dynamic
    static int attr_done = 0;
    if (!attr_done) {
        cudaFuncSetAttribute(fused_scan,
                             cudaFuncAttributeMaxDynamicSharedMemorySize, smem_bytes);
        attr_done = 1;
    }

    // U0[t][b][:] = x[b][t][:] @ W_in0^T + b0
    gemm_bias<true><<<dim3(8, 256), 256>>>(x, W_in0, b0, uptr, 1024, 256);

    // fused two-layer scan (layer 1 one step behind layer 0)
    fused_scan<<<128, 128, smem_bytes>>>(uptr, W_rec0, W_in1, W_rec1, b1,
                                         states0, states1);

    // output projection
    gemm_bias<false><<<dim3(2, 256), 256>>>(states1, W_out, b_out, out, 256, 1024);
}